// round 6
// baseline (speedup 1.0000x reference)
#include <cuda_runtime.h>
#include <cstdint>

// ParallelVarPatchEmbed via mma.sync m16n8k8 TF32 + cp.async 3-stage pipeline.
// Per CTA: D[128 x 128] = A[128 x 256] @ B^T + bias.  K chunks of 32, SW128-swizzled
// SMEM stages (no padding), 2 CTAs/SM.

static constexpr int THREADS = 256;

// SMEM (floats): bias[128] | A stages 3 x 4096 | B stages 3 x 4096
static constexpr int BIAS_OFF  = 0;
static constexpr int A_OFF     = 128;
static constexpr int B_OFF     = 128 + 3 * 4096;
static constexpr int SMEM_FLOATS = 128 + 6 * 4096;     // 24704
static constexpr int SMEM_BYTES  = SMEM_FLOATS * 4;    // 98816

__device__ __forceinline__ uint32_t smem_u32(const void* p) {
    uint32_t a;
    asm("{ .reg .u64 t; cvta.to.shared.u64 t, %1; cvt.u32.u64 %0, t; }" : "=r"(a) : "l"(p));
    return a;
}
__device__ __forceinline__ void cpasync16(uint32_t dst, const float* src) {
    asm volatile("cp.async.cg.shared.global [%0], [%1], 16;" :: "r"(dst), "l"(src) : "memory");
}
__device__ __forceinline__ void cpcommit() {
    asm volatile("cp.async.commit_group;" ::: "memory");
}
template <int N> __device__ __forceinline__ void cpwait() {
    asm volatile("cp.async.wait_group %0;" :: "n"(N) : "memory");
}
__device__ __forceinline__ uint32_t f2tf32(float f) {
    uint32_t r;
    asm("cvt.rna.tf32.f32 %0, %1;" : "=r"(r) : "f"(f));
    return r;
}
__device__ __forceinline__ void mma8(float* c, const uint32_t* a, uint32_t b0, uint32_t b1) {
    asm volatile(
        "mma.sync.aligned.m16n8k8.row.col.f32.tf32.tf32.f32 "
        "{%0,%1,%2,%3}, {%4,%5,%6,%7}, {%8,%9}, {%0,%1,%2,%3};"
        : "+f"(c[0]), "+f"(c[1]), "+f"(c[2]), "+f"(c[3])
        : "r"(a[0]), "r"(a[1]), "r"(a[2]), "r"(a[3]), "r"(b0), "r"(b1));
}
// swizzled float index within a 128x32 tile: word = m*32 + (k ^ ((m&7)*4))
__device__ __forceinline__ int swi(int m, int k) {
    return m * 32 + (k ^ ((m & 7) * 4));
}
// JAX demotes int64->int32 silently; detect layout from first 32 bytes.
__device__ __forceinline__ int get_var(const int* __restrict__ p32, int v) {
    bool is64 = ((p32[1] | p32[3] | p32[5] | p32[7]) == 0);
    return is64 ? p32[2 * v] : p32[v];
}

__global__ __launch_bounds__(THREADS, 2)
void pve_mma_kernel(const float* __restrict__ x,
                    const int* __restrict__ in_vars,
                    const float* __restrict__ w,
                    const float* __restrict__ bias,
                    float* __restrict__ out)
{
    extern __shared__ float smf[];
    const uint32_t sbase = smem_u32(smf);

    const int tid  = threadIdx.x;
    const int wid  = tid >> 5;
    const int lane = tid & 31;
    const int qrow = lane >> 2;
    const int qcol = lane & 3;
    const int m0   = (wid >> 1) * 32;
    const int n0   = (wid & 1) * 64;

    const int rg = blockIdx.x, v = blockIdx.y, b = blockIdx.z;
    const int var = get_var(in_vars, v);

    const float* xbase = x + (size_t)(b * 8 + v) * (512 * 512) + (size_t)rg * 64 * 512;
    const float* wbase = w + (size_t)var * (128 * 256);

    if (tid < 128) smf[BIAS_OFF + tid] = bias[var * 128 + tid];

    // per-thread constant parts of the copy mapping (4 segments each for A and B)
    // A: idx = tid + 256*i -> rl=idx>>7, c4=idx&127; pr=rl>>1, dp=rl&1
    // B: idx -> e=idx>>3, k4=idx&7

    auto issue_chunk = [&](int c, int slot) {
        const uint32_t abase = sbase + (A_OFF + slot * 4096) * 4;
        const uint32_t bbase = sbase + (B_OFF + slot * 4096) * 4;
        #pragma unroll
        for (int i = 0; i < 4; i++) {
            int idx = tid + 256 * i;
            int rl = idx >> 7, c4 = idx & 127;
            int pr = rl >> 1, dp = rl & 1;
            int m  = pr * 32 + (c4 >> 2);
            int kl = dp * 16 + (c4 & 3) * 4;
            cpasync16(abase + swi(m, kl) * 4,
                      xbase + (size_t)(pr * 16 + c * 2 + dp) * 512 + c4 * 4);
        }
        #pragma unroll
        for (int i = 0; i < 4; i++) {
            int idx = tid + 256 * i;
            int e  = idx >> 3;
            int kl = (idx & 7) * 4;
            cpasync16(bbase + swi(e, kl) * 4,
                      wbase + (size_t)e * 256 + c * 32 + kl);
        }
        cpcommit();
    };

    float acc[2][8][4];
    #pragma unroll
    for (int mf = 0; mf < 2; mf++)
        #pragma unroll
        for (int nf = 0; nf < 8; nf++)
            #pragma unroll
            for (int j = 0; j < 4; j++) acc[mf][nf][j] = 0.0f;

    // prologue: stages 0,1
    issue_chunk(0, 0);
    issue_chunk(1, 1);

    #pragma unroll
    for (int c = 0; c < 8; c++) {
        if (c + 2 < 8) issue_chunk(c + 2, (c + 2) % 3);
        // wait until chunk c's group is complete
        if (c < 6)      cpwait<2>();
        else if (c == 6) cpwait<1>();
        else             cpwait<0>();
        __syncthreads();

        const float* As = smf + A_OFF + (c % 3) * 4096;
        const float* Bs = smf + B_OFF + (c % 3) * 4096;
        #pragma unroll
        for (int ks = 0; ks < 4; ks++) {
            const int k0 = ks * 8;
            uint32_t a[2][4];
            #pragma unroll
            for (int mf = 0; mf < 2; mf++) {
                const int mb = m0 + mf * 16 + qrow;
                a[mf][0] = f2tf32(As[swi(mb,     k0 + qcol)]);
                a[mf][1] = f2tf32(As[swi(mb + 8, k0 + qcol)]);
                a[mf][2] = f2tf32(As[swi(mb,     k0 + qcol + 4)]);
                a[mf][3] = f2tf32(As[swi(mb + 8, k0 + qcol + 4)]);
            }
            #pragma unroll
            for (int nf = 0; nf < 8; nf++) {
                const int n = n0 + nf * 8 + qrow;
                uint32_t b0 = f2tf32(Bs[swi(n, k0 + qcol)]);
                uint32_t b1 = f2tf32(Bs[swi(n, k0 + qcol + 4)]);
                mma8(acc[0][nf], a[0], b0, b1);
                mma8(acc[1][nf], a[1], b0, b1);
            }
        }
        __syncthreads();   // slot (c%3) free for reuse by issue at iter c+1
    }

    // ---- epilogue: bias + store ----
    float* obase = out + (((size_t)(b * 8 + v) * 1024) + (size_t)rg * 128) * 128;
    const float* bs = smf + BIAS_OFF;
    #pragma unroll
    for (int mf = 0; mf < 2; mf++) {
        const int r = m0 + mf * 16 + qrow;
        #pragma unroll
        for (int nf = 0; nf < 8; nf++) {
            const int e0 = n0 + nf * 8 + qcol * 2;
            float2 lo, hi;
            lo.x = acc[mf][nf][0] + bs[e0];
            lo.y = acc[mf][nf][1] + bs[e0 + 1];
            hi.x = acc[mf][nf][2] + bs[e0];
            hi.y = acc[mf][nf][3] + bs[e0 + 1];
            *reinterpret_cast<float2*>(obase + (size_t)r * 128 + e0)       = lo;
            *reinterpret_cast<float2*>(obase + (size_t)(r + 8) * 128 + e0) = hi;
        }
    }
}

extern "C" void kernel_launch(void* const* d_in, const int* in_sizes, int n_in,
                              void* d_out, int out_size)
{
    const float* x       = (const float*)d_in[0];
    const int*   in_vars = (const int*)d_in[1];
    const float* w       = (const float*)d_in[2];
    const float* bias    = (const float*)d_in[3];
    float*       out     = (float*)d_out;

    cudaFuncSetAttribute(pve_mma_kernel,
                         cudaFuncAttributeMaxDynamicSharedMemorySize, SMEM_BYTES);

    dim3 grid(8, 8, 16);   // (row group, V, B) -> 1024 CTAs
    pve_mma_kernel<<<grid, THREADS, SMEM_BYTES>>>(x, in_vars, w, bias, out);
}

// round 7
// speedup vs baseline: 1.7013x; 1.7013x over previous
#include <cuda_runtime.h>
#include <cstdint>

// ParallelVarPatchEmbed, persistent-over-batch tf32 mma.sync kernel.
// Grid: 8(rg) x 8(v) x 2(bg) = 128 CTAs, one per SM-wave. Each CTA:
//   - loads W[var] (128x256) once, converts to tf32, keeps in SMEM (8 chunk-tiles)
//   - streams A (patches of x) for 8 batches through a 4-stage cp.async ring
//   - 64 chunk-iterations total, 1 barrier each; epilogue per finished b-tile.

static constexpr int THREADS = 256;

// SMEM floats: bias[128] | A ring 4 x 4096 | B 8 x 4096
static constexpr int BIAS_OFF = 0;
static constexpr int A_OFF    = 128;
static constexpr int B_OFF    = 128 + 4 * 4096;
static constexpr int SMEM_FLOATS = 128 + 12 * 4096;      // 49280
static constexpr int SMEM_BYTES  = SMEM_FLOATS * 4;      // 197120

__device__ __forceinline__ uint32_t smem_u32(const void* p) {
    uint32_t a;
    asm("{ .reg .u64 t; cvta.to.shared.u64 t, %1; cvt.u32.u64 %0, t; }" : "=r"(a) : "l"(p));
    return a;
}
__device__ __forceinline__ void cpasync16(uint32_t dst, const float* src) {
    asm volatile("cp.async.cg.shared.global [%0], [%1], 16;" :: "r"(dst), "l"(src) : "memory");
}
__device__ __forceinline__ void cpcommit() {
    asm volatile("cp.async.commit_group;" ::: "memory");
}
template <int N> __device__ __forceinline__ void cpwait() {
    asm volatile("cp.async.wait_group %0;" :: "n"(N) : "memory");
}
__device__ __forceinline__ uint32_t f2tf32(float f) {
    uint32_t r;
    asm("cvt.rna.tf32.f32 %0, %1;" : "=r"(r) : "f"(f));
    return r;
}
__device__ __forceinline__ void mma8(float* c, const uint32_t* a, uint32_t b0, uint32_t b1) {
    asm volatile(
        "mma.sync.aligned.m16n8k8.row.col.f32.tf32.tf32.f32 "
        "{%0,%1,%2,%3}, {%4,%5,%6,%7}, {%8,%9}, {%0,%1,%2,%3};"
        : "+f"(c[0]), "+f"(c[1]), "+f"(c[2]), "+f"(c[3])
        : "r"(a[0]), "r"(a[1]), "r"(a[2]), "r"(a[3]), "r"(b0), "r"(b1));
}
// swizzled float index within a 128x32 tile: word = m*32 + (k ^ ((m&7)*4))
__device__ __forceinline__ int swi(int m, int k) {
    return m * 32 + (k ^ ((m & 7) * 4));
}
// JAX demotes int64->int32 silently; detect layout from first 32 bytes.
__device__ __forceinline__ int get_var(const int* __restrict__ p32, int v) {
    bool is64 = ((p32[1] | p32[3] | p32[5] | p32[7]) == 0);
    return is64 ? p32[2 * v] : p32[v];
}

__global__ __launch_bounds__(THREADS, 1)
void pve_mma_kernel(const float* __restrict__ x,
                    const int* __restrict__ in_vars,
                    const float* __restrict__ w,
                    const float* __restrict__ bias,
                    float* __restrict__ out)
{
    extern __shared__ float smf[];
    const uint32_t sbase = smem_u32(smf);

    const int tid  = threadIdx.x;
    const int wid  = tid >> 5;
    const int lane = tid & 31;
    const int qrow = lane >> 2;
    const int qcol = lane & 3;
    const int m0   = (wid >> 1) * 32;
    const int n0   = (wid & 1) * 64;

    const int rg = blockIdx.x, v = blockIdx.y, bg = blockIdx.z;
    const int var = get_var(in_vars, v);

    const float* wbase = w + (size_t)var * (128 * 256);

    if (tid < 128) smf[BIAS_OFF + tid] = bias[var * 128 + tid];

    // ---- B prologue: load W[var] once, convert to tf32, 8 swizzled chunk-tiles ----
    #pragma unroll
    for (int i = 0; i < 32; i++) {
        int idx = tid + 256 * i;            // 0..8191 float4s
        int e   = idx >> 6;                 // 0..127
        int k4  = idx & 63;                 // float4 within 256-float row
        int ch  = k4 >> 3;                  // k-chunk 0..7
        int kl  = (k4 & 7) * 4;             // k within chunk
        float4 vsrc = *reinterpret_cast<const float4*>(wbase + (size_t)e * 256 + k4 * 4);
        uint4 t;
        t.x = f2tf32(vsrc.x); t.y = f2tf32(vsrc.y);
        t.z = f2tf32(vsrc.z); t.w = f2tf32(vsrc.w);
        *reinterpret_cast<uint4*>(smf + B_OFF + ch * 4096 + swi(e, kl)) = t;
    }

    // per-b A base pointer: b = bg*8 + bi
    auto xb = [&](int bi) {
        int b = bg * 8 + bi;
        return x + (size_t)(b * 8 + v) * (512 * 512) + (size_t)rg * 64 * 512;
    };

    // Issue A chunk t (t = bi*8 + ch) into ring slot t%4.
    auto issueA = [&](int t) {
        const int bi = t >> 3, ch = t & 7;
        const float* xbase = xb(bi);
        const uint32_t abase = sbase + (A_OFF + (t & 3) * 4096) * 4;
        #pragma unroll
        for (int i = 0; i < 4; i++) {
            int idx = tid + 256 * i;        // 0..1023 float4s
            int rl = idx >> 7, c4 = idx & 127;
            int pr = rl >> 1, dp = rl & 1;
            int m  = pr * 32 + (c4 >> 2);
            int kl = dp * 16 + (c4 & 3) * 4;
            cpasync16(abase + swi(m, kl) * 4,
                      xbase + (size_t)(pr * 16 + ch * 2 + dp) * 512 + c4 * 4);
        }
        cpcommit();
    };

    float acc[2][8][4];
    #pragma unroll
    for (int mf = 0; mf < 2; mf++)
        #pragma unroll
        for (int nf = 0; nf < 8; nf++)
            #pragma unroll
            for (int j = 0; j < 4; j++) acc[mf][nf][j] = 0.0f;

    // prologue: chunks 0,1,2 into slots 0,1,2
    issueA(0); issueA(1); issueA(2);

    #pragma unroll 1
    for (int t = 0; t < 64; t++) {
        if (t < 62)      cpwait<2>();
        else if (t == 62) cpwait<1>();
        else              cpwait<0>();
        __syncthreads();
        if (t + 3 < 64) issueA(t + 3);     // slot (t+3)%4 = (t-1)%4, consumed last iter

        const float* As = smf + A_OFF + (t & 3) * 4096;
        const float* Bs = smf + B_OFF + (t & 7) * 4096;
        #pragma unroll
        for (int ks = 0; ks < 4; ks++) {
            const int k0 = ks * 8;
            uint32_t a[2][4];
            #pragma unroll
            for (int mf = 0; mf < 2; mf++) {
                const int mb = m0 + mf * 16 + qrow;
                a[mf][0] = f2tf32(As[swi(mb,     k0 + qcol)]);
                a[mf][1] = f2tf32(As[swi(mb + 8, k0 + qcol)]);
                a[mf][2] = f2tf32(As[swi(mb,     k0 + qcol + 4)]);
                a[mf][3] = f2tf32(As[swi(mb + 8, k0 + qcol + 4)]);
            }
            #pragma unroll
            for (int nf = 0; nf < 8; nf++) {
                const int n = n0 + nf * 8 + qrow;
                uint32_t b0 = __float_as_uint(Bs[swi(n, k0 + qcol)]);
                uint32_t b1 = __float_as_uint(Bs[swi(n, k0 + qcol + 4)]);
                mma8(acc[0][nf], a[0], b0, b1);
                mma8(acc[1][nf], a[1], b0, b1);
            }
        }

        if ((t & 7) == 7) {
            // ---- epilogue for batch bi = t>>3 ----
            const int b = bg * 8 + (t >> 3);
            float* obase = out + (((size_t)(b * 8 + v) * 1024) + (size_t)rg * 128) * 128;
            const float* bs = smf + BIAS_OFF;
            #pragma unroll
            for (int mf = 0; mf < 2; mf++) {
                const int r = m0 + mf * 16 + qrow;
                #pragma unroll
                for (int nf = 0; nf < 8; nf++) {
                    const int e0 = n0 + nf * 8 + qcol * 2;
                    float2 lo, hi;
                    lo.x = acc[mf][nf][0] + bs[e0];
                    lo.y = acc[mf][nf][1] + bs[e0 + 1];
                    hi.x = acc[mf][nf][2] + bs[e0];
                    hi.y = acc[mf][nf][3] + bs[e0 + 1];
                    *reinterpret_cast<float2*>(obase + (size_t)r * 128 + e0)       = lo;
                    *reinterpret_cast<float2*>(obase + (size_t)(r + 8) * 128 + e0) = hi;
                    acc[mf][nf][0] = 0.0f; acc[mf][nf][1] = 0.0f;
                    acc[mf][nf][2] = 0.0f; acc[mf][nf][3] = 0.0f;
                }
            }
        }
    }
}

extern "C" void kernel_launch(void* const* d_in, const int* in_sizes, int n_in,
                              void* d_out, int out_size)
{
    const float* x       = (const float*)d_in[0];
    const int*   in_vars = (const int*)d_in[1];
    const float* w       = (const float*)d_in[2];
    const float* bias    = (const float*)d_in[3];
    float*       out     = (float*)d_out;

    cudaFuncSetAttribute(pve_mma_kernel,
                         cudaFuncAttributeMaxDynamicSharedMemorySize, SMEM_BYTES);

    dim3 grid(8, 8, 2);    // (row group, V, batch group) -> 128 persistent CTAs
    pve_mma_kernel<<<grid, THREADS, SMEM_BYTES>>>(x, in_vars, w, bias, out);
}